// round 1
// baseline (speedup 1.0000x reference)
#include <cuda_runtime.h>

#define Bdim 64
#define Hdim 64
#define Wdim 64
#define Cch  16
#define Fch  128
#define Dch  256
#define NPIX (Bdim * Hdim * Wdim)
#define TSTEPS 60

// Ping-pong grid state buffers (2 x 16 MB). Channel 0 is frozen (== input image).
__device__ float g_bufs[2][NPIX * Cch];

// Shared-memory layout (in floats)
#define S_IN 0                      // halo tile: 3 rows x 66 cols x 16 ch = 3168
#define S_H  3168                   // conv output: 64 x 128 = 8192
#define S_A  (3168 + 8192)          // dense1 output: 64 x 256 = 16384
#define S_W  (3168 + 8192 + 16384)  // weight staging: 4096
#define SMEM_FLOATS (3168 + 8192 + 16384 + 4096)  // 31840 floats = 127360 B

__global__ void nca_init(const float* __restrict__ input) {
    int pix = blockIdx.x * blockDim.x + threadIdx.x;
    if (pix < NPIX) {
        float* g = g_bufs[0] + (size_t)pix * Cch;
        g[0] = input[pix];
        #pragma unroll
        for (int c = 1; c < Cch; c++) g[c] = 0.0f;
    }
}

// One CTA = one (b,h) row of 64 pixels. 256 threads = 16(tx) x 16(ty).
// Thread (tx,ty) owns pixels m = 4*ty+i (i<4) and output columns n = tx + 16*j.
__global__ __launch_bounds__(256, 1) void nca_step(
    int sb,
    const float* __restrict__ cw, const float* __restrict__ cb,
    const float* __restrict__ w1, const float* __restrict__ b1,
    const float* __restrict__ w2, const float* __restrict__ b2)
{
    extern __shared__ float sm[];
    const float* __restrict__ gsrc = g_bufs[sb];
    float* __restrict__ gdst = g_bufs[sb ^ 1];

    const int tid = threadIdx.x;
    const int tx = tid & 15;
    const int ty = tid >> 4;
    const int b  = blockIdx.x >> 6;
    const int h  = blockIdx.x & 63;

    // ---- Load halo tile (rows h-1..h+1, cols -1..64, zero-padded) as float4 ----
    {
        float4* s4 = (float4*)(sm + S_IN);
        const float4* g4 = (const float4*)gsrc;  // 16 floats/pixel = 4 float4
        #pragma unroll
        for (int idx = tid; idx < 3 * 66 * 4; idx += 256) {
            int r   = idx / (66 * 4);
            int rem = idx - r * (66 * 4);
            int wc  = rem >> 2;
            int c4  = rem & 3;
            int hh = h + r - 1;
            int ww = wc - 1;
            float4 v = make_float4(0.f, 0.f, 0.f, 0.f);
            if (hh >= 0 && hh < Hdim && ww >= 0 && ww < Wdim)
                v = g4[(size_t)(((b * Hdim + hh) * Wdim + ww)) * 4 + c4];
            s4[idx] = v;
        }
    }

    // ---- Conv 3x3, 16 -> 128, as GEMM M=64, K=9*16, N=128 ----
    float cbf[8];
    #pragma unroll
    for (int j = 0; j < 8; j++) cbf[j] = __ldg(cb + tx + 16 * j);

    float acc[4][8];
    #pragma unroll
    for (int i = 0; i < 4; i++)
        #pragma unroll
        for (int j = 0; j < 8; j++) acc[i][j] = 0.0f;

    for (int t9 = 0; t9 < 9; t9++) {
        const int ky = t9 / 3, kx = t9 % 3;
        __syncthreads();  // also publishes s_in on first iteration
        {   // stage conv_w[ky][kx][:][:]: 16*128 floats = 512 float4
            float4* w4 = (float4*)(sm + S_W);
            const float4* g4 = (const float4*)(cw + t9 * (Cch * Fch));
            w4[tid]       = g4[tid];
            w4[tid + 256] = g4[tid + 256];
        }
        __syncthreads();
        #pragma unroll
        for (int ci = 0; ci < 16; ci++) {
            float a_[4];
            #pragma unroll
            for (int i = 0; i < 4; i++)
                a_[i] = sm[S_IN + (ky * 66 + (4 * ty + i) + kx) * 16 + ci];
            float b_[8];
            #pragma unroll
            for (int j = 0; j < 8; j++)
                b_[j] = sm[S_W + ci * 128 + tx + 16 * j];
            #pragma unroll
            for (int i = 0; i < 4; i++)
                #pragma unroll
                for (int j = 0; j < 8; j++)
                    acc[i][j] = fmaf(a_[i], b_[j], acc[i][j]);
        }
    }
    // write h = relu(conv + cb)
    #pragma unroll
    for (int i = 0; i < 4; i++) {
        int m = 4 * ty + i;
        #pragma unroll
        for (int j = 0; j < 8; j++) {
            float v = acc[i][j] + cbf[j];
            sm[S_H + m * 128 + tx + 16 * j] = v > 0.0f ? v : 0.0f;
        }
    }

    // ---- Dense1: M=64, K=128, N=256; a = relu(h @ w1 + b1) ----
    float b1f[16];
    #pragma unroll
    for (int j = 0; j < 16; j++) b1f[j] = __ldg(b1 + tx + 16 * j);

    float acc1[4][16];
    #pragma unroll
    for (int i = 0; i < 4; i++)
        #pragma unroll
        for (int j = 0; j < 16; j++) acc1[i][j] = 0.0f;

    for (int k0 = 0; k0 < 128; k0 += 16) {
        __syncthreads();
        {   // stage w1[k0:k0+16][:]: 16*256 floats = 1024 float4
            float4* w4 = (float4*)(sm + S_W);
            const float4* g4 = (const float4*)(w1 + k0 * Dch);
            #pragma unroll
            for (int u = 0; u < 4; u++) w4[tid + 256 * u] = g4[tid + 256 * u];
        }
        __syncthreads();
        #pragma unroll
        for (int kk = 0; kk < 16; kk++) {
            float a_[4];
            #pragma unroll
            for (int i = 0; i < 4; i++)
                a_[i] = sm[S_H + (4 * ty + i) * 128 + (k0 + kk)];
            float b_[16];
            #pragma unroll
            for (int j = 0; j < 16; j++)
                b_[j] = sm[S_W + kk * 256 + tx + 16 * j];
            #pragma unroll
            for (int i = 0; i < 4; i++)
                #pragma unroll
                for (int j = 0; j < 16; j++)
                    acc1[i][j] = fmaf(a_[i], b_[j], acc1[i][j]);
        }
    }
    // write a = relu(acc1 + b1)
    #pragma unroll
    for (int i = 0; i < 4; i++) {
        int m = 4 * ty + i;
        #pragma unroll
        for (int j = 0; j < 16; j++) {
            float v = acc1[i][j] + b1f[j];
            sm[S_A + m * 256 + tx + 16 * j] = v > 0.0f ? v : 0.0f;
        }
    }

    // ---- Dense2: M=64, K=256, N=16; d = a @ w2 + b2 ----
    __syncthreads();
    {   // stage full w2: 256*16 floats = 1024 float4
        float4* w4 = (float4*)(sm + S_W);
        const float4* g4 = (const float4*)w2;
        #pragma unroll
        for (int u = 0; u < 4; u++) w4[tid + 256 * u] = g4[tid + 256 * u];
    }
    __syncthreads();

    float acc2[4] = {0.f, 0.f, 0.f, 0.f};
    #pragma unroll 8
    for (int k = 0; k < 256; k++) {
        float bv = sm[S_W + k * 16 + tx];
        #pragma unroll
        for (int i = 0; i < 4; i++)
            acc2[i] = fmaf(sm[S_A + (4 * ty + i) * 256 + k], bv, acc2[i]);
    }

    // ---- Residual update: g += d * (c != 0) * (g[...,0] > 0.1) ----
    const float b2v = __ldg(b2 + tx);
    const size_t pixbase = (size_t)blockIdx.x * 64 * Cch;
    #pragma unroll
    for (int i = 0; i < 4; i++) {
        int m = 4 * ty + i;
        float oldv  = sm[S_IN + (66 + (m + 1)) * 16 + tx];   // center row of halo
        bool  alive = sm[S_IN + (66 + (m + 1)) * 16 + 0] > 0.1f;
        float dd = acc2[i] + b2v;
        float nv = oldv;
        if (tx != 0 && alive) nv += dd;
        gdst[pixbase + (size_t)m * Cch + tx] = nv;
    }
}

__global__ void nca_softmax(float* __restrict__ out) {
    int pix = blockIdx.x * blockDim.x + threadIdx.x;
    if (pix >= NPIX) return;
    const float* g = g_bufs[0] + (size_t)pix * Cch;
    float v[10];
    #pragma unroll
    for (int c = 0; c < 10; c++) v[c] = g[1 + c];
    float mx = v[0];
    #pragma unroll
    for (int c = 1; c < 10; c++) mx = fmaxf(mx, v[c]);
    float s = 0.0f;
    #pragma unroll
    for (int c = 0; c < 10; c++) { v[c] = __expf(v[c] - mx); s += v[c]; }
    float inv = 1.0f / s;
    float* o = out + (size_t)pix * 10;
    #pragma unroll
    for (int c = 0; c < 10; c++) o[c] = v[c] * inv;
}

extern "C" void kernel_launch(void* const* d_in, const int* in_sizes, int n_in,
                              void* d_out, int out_size) {
    const float* input = (const float*)d_in[0];
    const float* cw    = (const float*)d_in[1];
    const float* cb    = (const float*)d_in[2];
    const float* w1    = (const float*)d_in[3];
    const float* b1    = (const float*)d_in[4];
    const float* w2    = (const float*)d_in[5];
    const float* b2    = (const float*)d_in[6];

    const int smem_bytes = SMEM_FLOATS * 4;  // 127360 B
    cudaFuncSetAttribute(nca_step, cudaFuncAttributeMaxDynamicSharedMemorySize, smem_bytes);

    nca_init<<<NPIX / 256, 256>>>(input);
    for (int t = 0; t < TSTEPS; t++) {
        nca_step<<<Bdim * Hdim, 256, smem_bytes>>>(t & 1, cw, cb, w1, b1, w2, b2);
    }
    nca_softmax<<<NPIX / 256, 256>>>((float*)d_out);
}

// round 2
// speedup vs baseline: 1.4420x; 1.4420x over previous
#include <cuda_runtime.h>

#define Bdim 64
#define Hdim 64
#define Wdim 64
#define Cch  16
#define Fch  128
#define Dch  256
#define NPIX (Bdim * Hdim * Wdim)
#define TSTEPS 60

typedef unsigned long long u64;

__device__ float g_bufs[2][NPIX * Cch];

// ---- f32x2 packed helpers ----
__device__ __forceinline__ u64 pack2(float lo, float hi) {
    u64 r; asm("mov.b64 %0, {%1, %2};" : "=l"(r) : "f"(lo), "f"(hi)); return r;
}
__device__ __forceinline__ u64 dup2(float v) { return pack2(v, v); }
__device__ __forceinline__ void unpack2(u64 v, float& lo, float& hi) {
    asm("mov.b64 {%0, %1}, %2;" : "=f"(lo), "=f"(hi) : "l"(v));
}
__device__ __forceinline__ u64 fma2(u64 a, u64 b, u64 c) {
    u64 d; asm("fma.rn.f32x2 %0, %1, %2, %3;" : "=l"(d) : "l"(a), "l"(b), "l"(c)); return d;
}

// ---- shared layout (float indices; all even) ----
#define S_IN  0                         // halo: 3 x 66 x 16 = 3168
#define S_H   3168                      // conv out: 64 x 128 = 8192
#define S_W1  (3168 + 8192)             // w1 chunk: 64 x 256 = 16384
#define S_CW  (S_W1 + 16384)            // conv w: 9*16*128 = 18432 (reused as d2 partials)
#define S_W2  (S_CW + 18432)            // w2 pairs: 256 x 18 = 4608
#define SMEM_FLOATS (S_W2 + 4608)       // 50784 floats = 203136 B

__global__ void nca_init(const float* __restrict__ input) {
    int pix = blockIdx.x * blockDim.x + threadIdx.x;
    if (pix < NPIX) {
        float* g = g_bufs[0] + (size_t)pix * Cch;
        g[0] = input[pix];
        #pragma unroll
        for (int c = 1; c < Cch; c++) g[c] = 0.0f;
    }
}

// One CTA = one (b,h) row of 64 pixels. 256 threads = 16(tx) x 16(ty).
// Thread (tx,ty): rows m = 4*ty+i; paired output columns n = 2*tx + 32*j.
__global__ __launch_bounds__(256, 1) void nca_step(
    int sb,
    const float* __restrict__ cw, const float* __restrict__ cb,
    const float* __restrict__ w1, const float* __restrict__ b1,
    const float* __restrict__ w2, const float* __restrict__ b2)
{
    extern __shared__ float sm[];
    const float* __restrict__ gsrc = g_bufs[sb];
    float* __restrict__ gdst = g_bufs[sb ^ 1];

    const int tid = threadIdx.x;
    const int tx = tid & 15;
    const int ty = tid >> 4;
    const int b  = blockIdx.x >> 6;
    const int h  = blockIdx.x & 63;

    // ---- Stage halo tile (rows h-1..h+1, cols -1..64, zero-padded) ----
    {
        float4* s4 = (float4*)(sm + S_IN);
        const float4* g4 = (const float4*)gsrc;
        #pragma unroll
        for (int idx = tid; idx < 3 * 66 * 4; idx += 256) {
            int r   = idx / (66 * 4);
            int rem = idx - r * (66 * 4);
            int wc  = rem >> 2;
            int c4  = rem & 3;
            int hh = h + r - 1;
            int ww = wc - 1;
            float4 v = make_float4(0.f, 0.f, 0.f, 0.f);
            if (hh >= 0 && hh < Hdim && ww >= 0 && ww < Wdim)
                v = g4[(size_t)(((b * Hdim + hh) * Wdim + ww)) * 4 + c4];
            s4[idx] = v;
        }
    }
    // ---- Stage all conv weights (9*16*128 floats = 4608 float4) ----
    {
        float4* s4 = (float4*)(sm + S_CW);
        const float4* g4 = (const float4*)cw;
        #pragma unroll
        for (int u = 0; u < 18; u++) s4[tid + 256 * u] = g4[tid + 256 * u];
    }
    // ---- Stage w2 as padded pairs: dst[k*9 + c'] = w2 pair (k, 2c') ----
    {
        u64* dst = (u64*)(sm + S_W2);
        const u64* src = (const u64*)w2;
        #pragma unroll
        for (int u = 0; u < 8; u++) {
            int idx = tid + 256 * u;           // 0..2047
            int k = idx >> 3, c = idx & 7;
            dst[k * 9 + c] = src[idx];
        }
    }
    __syncthreads();

    // ============ Conv 3x3, 16 -> 128 (pairs) ============
    u64 accC[4][4];
    {
        const u64* cbp = (const u64*)cb;
        #pragma unroll
        for (int j = 0; j < 4; j++) {
            u64 bj = cbp[tx + 16 * j];
            #pragma unroll
            for (int i = 0; i < 4; i++) accC[i][j] = bj;
        }
    }
    for (int ky = 0; ky < 3; ky++) {
        for (int kx = 0; kx < 3; kx++) {
            const float* ap = sm + S_IN + (ky * 66 + kx + 4 * ty) * 16;
            const u64*  bw = (const u64*)(sm + S_CW + ((ky * 3 + kx) * 16) * 128);
            #pragma unroll
            for (int ci = 0; ci < 16; ci++) {
                u64 a0 = dup2(ap[ci]);
                u64 a1 = dup2(ap[16 + ci]);
                u64 a2 = dup2(ap[32 + ci]);
                u64 a3 = dup2(ap[48 + ci]);
                const u64* brow = bw + ci * 64 + tx;
                #pragma unroll
                for (int j = 0; j < 4; j++) {
                    u64 bj = brow[16 * j];
                    accC[0][j] = fma2(a0, bj, accC[0][j]);
                    accC[1][j] = fma2(a1, bj, accC[1][j]);
                    accC[2][j] = fma2(a2, bj, accC[2][j]);
                    accC[3][j] = fma2(a3, bj, accC[3][j]);
                }
            }
        }
    }
    // h = relu(conv); store pairs to S_H ([m][64] u64)
    {
        u64* hp = (u64*)(sm + S_H);
        #pragma unroll
        for (int i = 0; i < 4; i++) {
            int m = 4 * ty + i;
            #pragma unroll
            for (int j = 0; j < 4; j++) {
                float lo, hi; unpack2(accC[i][j], lo, hi);
                lo = fmaxf(lo, 0.0f); hi = fmaxf(hi, 0.0f);
                hp[m * 64 + tx + 16 * j] = pack2(lo, hi);
            }
        }
    }
    __syncthreads();

    // ============ Dense1: 128 -> 256 (pairs, full j=0..7) ============
    u64 acc1[4][8];
    {
        const u64* b1p = (const u64*)b1;
        #pragma unroll
        for (int j = 0; j < 8; j++) {
            u64 bj = b1p[tx + 16 * j];
            #pragma unroll
            for (int i = 0; i < 4; i++) acc1[i][j] = bj;
        }
    }
    for (int kc = 0; kc < 2; kc++) {
        __syncthreads();
        {   // stage w1[kc*64 .. +64][256] = 4096 float4
            float4* s4 = (float4*)(sm + S_W1);
            const float4* g4 = (const float4*)(w1 + kc * 64 * Dch);
            #pragma unroll
            for (int u = 0; u < 16; u++) s4[tid + 256 * u] = g4[tid + 256 * u];
        }
        __syncthreads();
        const float* hbase = sm + S_H + (4 * ty) * 128 + kc * 64;
        #pragma unroll 8
        for (int kk = 0; kk < 64; kk++) {
            u64 a0 = dup2(hbase[kk]);
            u64 a1 = dup2(hbase[128 + kk]);
            u64 a2 = dup2(hbase[256 + kk]);
            u64 a3 = dup2(hbase[384 + kk]);
            const u64* brow = (const u64*)(sm + S_W1) + kk * 128 + tx;
            #pragma unroll
            for (int j = 0; j < 8; j++) {
                u64 bj = brow[16 * j];
                acc1[0][j] = fma2(a0, bj, acc1[0][j]);
                acc1[1][j] = fma2(a1, bj, acc1[1][j]);
                acc1[2][j] = fma2(a2, bj, acc1[2][j]);
                acc1[3][j] = fma2(a3, bj, acc1[3][j]);
            }
        }
    }

    // ============ Dense2 fused in registers: d partials over c-pairs ============
    u64 acc2[4][8];
    #pragma unroll
    for (int i = 0; i < 4; i++)
        #pragma unroll
        for (int c = 0; c < 8; c++) acc2[i][c] = 0ull;

    #pragma unroll
    for (int j = 0; j < 8; j++) {
        float a_lo[4], a_hi[4];
        #pragma unroll
        for (int i = 0; i < 4; i++) {
            float lo, hi; unpack2(acc1[i][j], lo, hi);
            a_lo[i] = fmaxf(lo, 0.0f);
            a_hi[i] = fmaxf(hi, 0.0f);
        }
        #pragma unroll
        for (int e = 0; e < 2; e++) {
            int k = 2 * tx + 32 * j + e;
            const u64* w2row = (const u64*)(sm + S_W2) + k * 9;
            u64 av[4];
            #pragma unroll
            for (int i = 0; i < 4; i++) av[i] = dup2(e ? a_hi[i] : a_lo[i]);
            #pragma unroll
            for (int c = 0; c < 8; c++) {
                u64 wv = w2row[c];
                acc2[0][c] = fma2(av[0], wv, acc2[0][c]);
                acc2[1][c] = fma2(av[1], wv, acc2[1][c]);
                acc2[2][c] = fma2(av[2], wv, acc2[2][c]);
                acc2[3][c] = fma2(av[3], wv, acc2[3][c]);
            }
        }
    }

    // ---- cross-lane reduce via shared (reuse conv-weight region) ----
    // part[(m*8 + c') * 17 + g] (u64), g = tx
    {
        u64* part = (u64*)(sm + S_CW);
        __syncthreads();   // everyone past conv-weight reads; also orders w1 use
        #pragma unroll
        for (int i = 0; i < 4; i++) {
            int m = 4 * ty + i;
            #pragma unroll
            for (int c = 0; c < 8; c++)
                part[(m * 8 + c) * 17 + tx] = acc2[i][c];
        }
        __syncthreads();
    }

    // ---- reduce 16 partials, add b2, residual update, write out ----
    {
        const float* pf = sm + S_CW;  // float view of partials
        const float b2v = __ldg(b2 + tx);
        const int cpr = tx >> 1, comp = tx & 1;
        const size_t pixbase = (size_t)blockIdx.x * 64 * Cch;
        #pragma unroll
        for (int i = 0; i < 4; i++) {
            int m = 4 * ty + i;
            int basef = ((m * 8 + cpr) * 17) * 2 + comp;
            float s = 0.0f;
            #pragma unroll
            for (int g = 0; g < 16; g++) s += pf[basef + 2 * g];
            float dd = s + b2v;
            float oldv  = sm[S_IN + (66 + m + 1) * 16 + tx];
            bool  alive = sm[S_IN + (66 + m + 1) * 16] > 0.1f;
            float nv = oldv;
            if (tx != 0 && alive) nv += dd;
            gdst[pixbase + (size_t)m * Cch + tx] = nv;
        }
    }
}

__global__ void nca_softmax(float* __restrict__ out) {
    int pix = blockIdx.x * blockDim.x + threadIdx.x;
    if (pix >= NPIX) return;
    const float* g = g_bufs[0] + (size_t)pix * Cch;
    float v[10];
    #pragma unroll
    for (int c = 0; c < 10; c++) v[c] = g[1 + c];
    float mx = v[0];
    #pragma unroll
    for (int c = 1; c < 10; c++) mx = fmaxf(mx, v[c]);
    float s = 0.0f;
    #pragma unroll
    for (int c = 0; c < 10; c++) { v[c] = __expf(v[c] - mx); s += v[c]; }
    float inv = 1.0f / s;
    float* o = out + (size_t)pix * 10;
    #pragma unroll
    for (int c = 0; c < 10; c++) o[c] = v[c] * inv;
}

extern "C" void kernel_launch(void* const* d_in, const int* in_sizes, int n_in,
                              void* d_out, int out_size) {
    const float* input = (const float*)d_in[0];
    const float* cw    = (const float*)d_in[1];
    const float* cb    = (const float*)d_in[2];
    const float* w1    = (const float*)d_in[3];
    const float* b1    = (const float*)d_in[4];
    const float* w2    = (const float*)d_in[5];
    const float* b2    = (const float*)d_in[6];

    const int smem_bytes = SMEM_FLOATS * 4;  // 203136 B
    cudaFuncSetAttribute(nca_step, cudaFuncAttributeMaxDynamicSharedMemorySize, smem_bytes);

    nca_init<<<NPIX / 256, 256>>>(input);
    for (int t = 0; t < TSTEPS; t++) {
        nca_step<<<Bdim * Hdim, 256, smem_bytes>>>(t & 1, cw, cb, w1, b1, w2, b2);
    }
    nca_softmax<<<NPIX / 256, 256>>>((float*)d_out);
}